// round 10
// baseline (speedup 1.0000x reference)
#include <cuda_runtime.h>
#include <cuda_bf16.h>
#include <cstdint>

#define NN     16384
#define BATCH  2
#define CIN    128
#define OUTC   128
#define HTOT   256
#define DHW    8192
#define EMAX   262144
#define NEG_ATT 0.2f
#define NEG_ACT 0.01f
#define BN_EPS 1e-5f
#define GEMM_BLOCKS 512       // NN/32

// ---------------- device scratch ----------------
__device__ float g_h[(size_t)NN * HTOT];     // 16 MB
__device__ float g_pre[(size_t)NN * OUTC];   // 8 MB
__device__ int   g_counts[NN];               // zero-init at load; re-zeroed by k_scatter
__device__ int   g_rowstart[NN + 1];
__device__ int   g_cursor[NN];
__device__ int   g_esrc[EMAX];
__device__ float g_sum[OUTC];                // zero-init; re-zeroed by k_scatter
__device__ float g_sumsq[OUTC];

// ---------------- K1: gemm + edge-count fused (independent work) ----------------
// blocks [0, 512): h = xf @ W + b via packed f32x2 FMA
// blocks [512, ..): histogram of dst into g_counts
__global__ __launch_bounds__(256) void k_gc(const float* __restrict__ x,
                                            const float* __restrict__ w,
                                            const float* __restrict__ bias,
                                            const int* __restrict__ ei, int E) {
    __shared__ float sxT[128 * 32];   // [k][node]
    int t = threadIdx.x;
    if (blockIdx.x >= GEMM_BLOCKS) {
        int e = (blockIdx.x - GEMM_BLOCKS) * 256 + t;
        if (e < E) atomicAdd(&g_counts[ei[E + e]], 1);
        return;
    }
    int n0 = blockIdx.x * 32;
    int b  = n0 >> 13;
    int s0 = n0 & 8191;

    const float* xb = x + (size_t)b * (CIN * DHW) + s0;
    for (int idx = t; idx < 128 * 32; idx += 256) {
        int k = idx >> 5, j = idx & 31;
        sxT[idx] = xb[(size_t)k * DHW + j];
    }
    __syncthreads();

    unsigned long long acc[16];
#pragma unroll
    for (int p = 0; p < 16; p++) acc[p] = 0ull;

    const float* wp = w + t;
    for (int k0 = 0; k0 < 128; k0 += 8) {
        float wr[8];
#pragma unroll
        for (int k = 0; k < 8; k++) wr[k] = wp[(size_t)(k0 + k) * HTOT];
#pragma unroll
        for (int k = 0; k < 8; k++) {
            unsigned long long wpk;
            asm("mov.b64 %0, {%1, %1};" : "=l"(wpk) : "r"(__float_as_uint(wr[k])));
            const unsigned long long* row =
                (const unsigned long long*)(sxT + (k0 + k) * 32);
#pragma unroll
            for (int p = 0; p < 16; p++) {
                asm("fma.rn.f32x2 %0, %1, %2, %0;"
                    : "+l"(acc[p]) : "l"(row[p]), "l"(wpk));
            }
        }
    }

    float bv = bias[t];
#pragma unroll
    for (int p = 0; p < 16; p++) {
        unsigned int lo, hi;
        asm("mov.b64 {%0, %1}, %2;" : "=r"(lo), "=r"(hi) : "l"(acc[p]));
        g_h[(size_t)(n0 + 2 * p)     * HTOT + t] = __uint_as_float(lo) + bv;
        g_h[(size_t)(n0 + 2 * p + 1) * HTOT + t] = __uint_as_float(hi) + bv;
    }
}

// ---------------- K2: single-block scan over counts ----------------
__global__ void k_scan() {
    __shared__ int part[512];
    int t = threadIdx.x;
    int base = t * 32;
    int s = 0;
#pragma unroll
    for (int i = 0; i < 32; i++) s += g_counts[base + i];
    part[t] = s;
    __syncthreads();
    for (int off = 1; off < 512; off <<= 1) {
        int v = (t >= off) ? part[t - off] : 0;
        __syncthreads();
        part[t] += v;
        __syncthreads();
    }
    int run = part[t] - s;
#pragma unroll
    for (int i = 0; i < 32; i++) {
        int c = g_counts[base + i];
        g_rowstart[base + i] = run;
        g_cursor[base + i] = run;
        run += c;
    }
    if (t == 511) g_rowstart[NN] = run;
}

// ---------------- K3: scatter + re-zero state for next graph replay ----------------
__global__ void k_scatter(const int* __restrict__ ei, int E) {
    int e = blockIdx.x * blockDim.x + threadIdx.x;
    if (e < E) {
        int s = ei[e];
        int d = ei[E + e];
        g_esrc[atomicAdd(&g_cursor[d], 1)] = s;
    }
    if (e < NN) g_counts[e] = 0;                    // ready for next replay's count
    if (e < OUTC) { g_sum[e] = 0.f; g_sumsq[e] = 0.f; }  // ready for k_agg's BN partials
}

// ---------------- K4: GATv2 aggregation + fused BN partial reduction ----------------
// one warp per dst node; un-stabilized softmax (logits O(+-10), fp32-safe);
// 4-edge unroll for shuffle/exp latency overlap.
__global__ __launch_bounds__(256) void k_agg(const float* __restrict__ att,
                                             const float* __restrict__ gbias) {
    __shared__ float bs[128], bq[128];
    int t = threadIdx.x;
    if (t < 128) { bs[t] = 0.f; bq[t] = 0.f; }
    __syncthreads();

    int lane = t & 31;
    int n = blockIdx.x * 8 + (t >> 5);
    int off = lane * 8;

    float av[8], hd[8];
    {
        float4 a0 = *(const float4*)(att + off);
        float4 a1 = *(const float4*)(att + off + 4);
        av[0]=a0.x; av[1]=a0.y; av[2]=a0.z; av[3]=a0.w;
        av[4]=a1.x; av[5]=a1.y; av[6]=a1.z; av[7]=a1.w;
        const float* hr = g_h + (size_t)n * HTOT + off;
        float4 d0 = *(const float4*)(hr);
        float4 d1 = *(const float4*)(hr + 4);
        hd[0]=d0.x; hd[1]=d0.y; hd[2]=d0.z; hd[3]=d0.w;
        hd[4]=d1.x; hd[5]=d1.y; hd[6]=d1.z; hd[7]=d1.w;
    }

    // self-loop
    float loc = 0.f;
#pragma unroll
    for (int i = 0; i < 8; i++) {
        float v = 2.f * hd[i];
        v = fmaxf(v, NEG_ATT * v);
        loc = fmaf(av[i], v, loc);
    }
#pragma unroll
    for (int o = 8; o >= 1; o >>= 1) loc += __shfl_xor_sync(0xffffffffu, loc, o);
    float ps = __expf(loc);
    float den = ps;
    float acc[8];
#pragma unroll
    for (int i = 0; i < 8; i++) acc[i] = ps * hd[i];

    int rs = g_rowstart[n];
    int re = g_rowstart[n + 1];
    int j = rs;
    for (; j + 4 <= re; j += 4) {
        int si0 = g_esrc[j], si1 = g_esrc[j+1], si2 = g_esrc[j+2], si3 = g_esrc[j+3];
        const float* r0 = g_h + (size_t)si0 * HTOT + off;
        const float* r1 = g_h + (size_t)si1 * HTOT + off;
        const float* r2 = g_h + (size_t)si2 * HTOT + off;
        const float* r3 = g_h + (size_t)si3 * HTOT + off;
        float4 x00 = *(const float4*)(r0), x01 = *(const float4*)(r0 + 4);
        float4 x10 = *(const float4*)(r1), x11 = *(const float4*)(r1 + 4);
        float4 x20 = *(const float4*)(r2), x21 = *(const float4*)(r2 + 4);
        float4 x30 = *(const float4*)(r3), x31 = *(const float4*)(r3 + 4);
        float hs0[8] = {x00.x,x00.y,x00.z,x00.w,x01.x,x01.y,x01.z,x01.w};
        float hs1[8] = {x10.x,x10.y,x10.z,x10.w,x11.x,x11.y,x11.z,x11.w};
        float hs2[8] = {x20.x,x20.y,x20.z,x20.w,x21.x,x21.y,x21.z,x21.w};
        float hs3[8] = {x30.x,x30.y,x30.z,x30.w,x31.x,x31.y,x31.z,x31.w};
        float l0 = 0.f, l1 = 0.f, l2 = 0.f, l3 = 0.f;
#pragma unroll
        for (int i = 0; i < 8; i++) {
            float v0 = hd[i] + hs0[i]; v0 = fmaxf(v0, NEG_ATT * v0); l0 = fmaf(av[i], v0, l0);
            float v1 = hd[i] + hs1[i]; v1 = fmaxf(v1, NEG_ATT * v1); l1 = fmaf(av[i], v1, l1);
            float v2 = hd[i] + hs2[i]; v2 = fmaxf(v2, NEG_ATT * v2); l2 = fmaf(av[i], v2, l2);
            float v3 = hd[i] + hs3[i]; v3 = fmaxf(v3, NEG_ATT * v3); l3 = fmaf(av[i], v3, l3);
        }
#pragma unroll
        for (int o = 8; o >= 1; o >>= 1) {
            l0 += __shfl_xor_sync(0xffffffffu, l0, o);
            l1 += __shfl_xor_sync(0xffffffffu, l1, o);
            l2 += __shfl_xor_sync(0xffffffffu, l2, o);
            l3 += __shfl_xor_sync(0xffffffffu, l3, o);
        }
        float p0 = __expf(l0), p1 = __expf(l1), p2 = __expf(l2), p3 = __expf(l3);
        den += (p0 + p1) + (p2 + p3);
#pragma unroll
        for (int i = 0; i < 8; i++)
            acc[i] = fmaf(p3, hs3[i], fmaf(p2, hs2[i],
                     fmaf(p1, hs1[i], fmaf(p0, hs0[i], acc[i]))));
    }
    for (; j < re; j++) {
        int si = g_esrc[j];
        const float* r0 = g_h + (size_t)si * HTOT + off;
        float4 x0 = *(const float4*)(r0), x1 = *(const float4*)(r0 + 4);
        float hs0[8] = {x0.x,x0.y,x0.z,x0.w,x1.x,x1.y,x1.z,x1.w};
        float l0 = 0.f;
#pragma unroll
        for (int i = 0; i < 8; i++) {
            float v0 = hd[i] + hs0[i];
            v0 = fmaxf(v0, NEG_ATT * v0);
            l0 = fmaf(av[i], v0, l0);
        }
#pragma unroll
        for (int o = 8; o >= 1; o >>= 1) l0 += __shfl_xor_sync(0xffffffffu, l0, o);
        float p0 = __expf(l0);
        den += p0;
#pragma unroll
        for (int i = 0; i < 8; i++) acc[i] = fmaf(p0, hs0[i], acc[i]);
    }

    float inv = 1.f / den;
    float v8[8], o8[8];
#pragma unroll
    for (int i = 0; i < 8; i++) v8[i] = acc[i] * inv;
#pragma unroll
    for (int i = 0; i < 8; i++) {
        float other = __shfl_down_sync(0xffffffffu, v8[i], 16);
        o8[i] = 0.5f * (v8[i] + other);
    }
    if (lane < 16) {
#pragma unroll
        for (int i = 0; i < 8; i++) {
            float vv = o8[i] + gbias[off + i];
            o8[i] = vv;
            atomicAdd(&bs[off + i], vv);
            atomicAdd(&bq[off + i], vv * vv);
        }
        float* op = g_pre + (size_t)n * OUTC + off;
        *(float4*)(op)     = make_float4(o8[0], o8[1], o8[2], o8[3]);
        *(float4*)(op + 4) = make_float4(o8[4], o8[5], o8[6], o8[7]);
    }
    __syncthreads();
    if (t < 128) {
        atomicAdd(&g_sum[t], bs[t]);
        atomicAdd(&g_sumsq[t], bq[t]);
    }
}

// ---------------- K5: BN finalize + transpose + LeakyReLU ----------------
__global__ __launch_bounds__(256) void k_apply(const float* __restrict__ gamma,
                                               const float* __restrict__ beta,
                                               float* __restrict__ out) {
    __shared__ float tile[128 * 33];
    __shared__ float sc[128], sh[128];
    int t = threadIdx.x;
    if (t < 128) {
        float mean = g_sum[t] * (1.f / NN);
        float var  = g_sumsq[t] * (1.f / NN) - mean * mean;
        float inv  = rsqrtf(var + BN_EPS);
        float s    = gamma[t] * inv;
        sc[t] = s;
        sh[t] = beta[t] - mean * s;
    }
    int n0 = blockIdx.x * 32;
    for (int idx = t; idx < 4096; idx += 256) {
        int row = idx >> 7;
        int col = idx & 127;
        tile[col * 33 + row] = g_pre[(size_t)(n0 + row) * OUTC + col];
    }
    __syncthreads();
    int b  = n0 >> 13;
    int s0 = n0 & 8191;
    int sl = t & 31;
    int c0 = t >> 5;
    float* ob = out + (size_t)b * OUTC * DHW + s0 + sl;
#pragma unroll
    for (int pass = 0; pass < 16; pass++) {
        int c = pass * 8 + c0;
        float v = tile[c * 33 + sl];
        v = fmaf(v, sc[c], sh[c]);
        v = fmaxf(v, NEG_ACT * v);
        ob[(size_t)c * DHW] = v;
    }
}

// ---------------- launcher ----------------
extern "C" void kernel_launch(void* const* d_in, const int* in_sizes, int n_in,
                              void* d_out, int out_size) {
    const float* x     = (const float*)d_in[0];
    const int*   ei    = (const int*)d_in[1];
    const float* lin_w = (const float*)d_in[2];
    const float* lin_b = (const float*)d_in[3];
    const float* att   = (const float*)d_in[4];
    const float* gbias = (const float*)d_in[5];
    const float* gamma = (const float*)d_in[6];
    const float* beta  = (const float*)d_in[7];
    float* out = (float*)d_out;

    int E  = in_sizes[1] / 2;
    int cb = (E + 255) / 256;

    k_gc<<<GEMM_BLOCKS + cb, 256>>>(x, lin_w, lin_b, ei, E);
    k_scan<<<1, 512>>>();
    k_scatter<<<cb, 256>>>(ei, E);
    k_agg<<<NN / 8, 256>>>(att, gbias);
    k_apply<<<NN / 32, 256>>>(gamma, beta, out);
}

// round 11
// speedup vs baseline: 1.6417x; 1.6417x over previous
#include <cuda_runtime.h>
#include <cuda_bf16.h>
#include <cstdint>

#define NN     16384
#define BATCH  2
#define CIN    128
#define OUTC   128
#define HTOT   256
#define DHW    8192
#define EMAX   262144
#define NEG_ATT 0.2f
#define NEG_ACT 0.01f
#define BN_EPS 1e-5f

// ---------------- device scratch ----------------
__device__ float g_h[(size_t)NN * HTOT];     // 16 MB
__device__ float g_pre[(size_t)NN * OUTC];   // 8 MB
__device__ int   g_counts[NN];               // zero at load; re-zeroed by k_scatter
__device__ int   g_rowstart[NN + 1];
__device__ int   g_cursor[NN];
__device__ int   g_esrc[EMAX];
__device__ float g_sum[OUTC];                // zero at load; re-zeroed by k_scatter
__device__ float g_sumsq[OUTC];

// ---------------- K1: count (4 edges/thread for MLP) ----------------
__global__ void k_count(const int* __restrict__ ei, int E) {
    int t4 = (blockIdx.x * blockDim.x + threadIdx.x) * 4;
    if (t4 + 4 <= E) {
        int4 d = *(const int4*)(ei + E + t4);
        atomicAdd(&g_counts[d.x], 1);
        atomicAdd(&g_counts[d.y], 1);
        atomicAdd(&g_counts[d.z], 1);
        atomicAdd(&g_counts[d.w], 1);
    } else {
        for (int e = t4; e < E; e++) atomicAdd(&g_counts[ei[E + e]], 1);
    }
}

// ---------------- K2: single-block scan ----------------
__global__ void k_scan() {
    __shared__ int part[512];
    int t = threadIdx.x;
    int base = t * 32;
    int s = 0;
#pragma unroll
    for (int i = 0; i < 32; i++) s += g_counts[base + i];
    part[t] = s;
    __syncthreads();
    for (int off = 1; off < 512; off <<= 1) {
        int v = (t >= off) ? part[t - off] : 0;
        __syncthreads();
        part[t] += v;
        __syncthreads();
    }
    int run = part[t] - s;
#pragma unroll
    for (int i = 0; i < 32; i++) {
        int c = g_counts[base + i];
        g_rowstart[base + i] = run;
        g_cursor[base + i] = run;
        run += c;
    }
    if (t == 511) g_rowstart[NN] = run;
}

// ---------------- K3: scatter (4 edges/thread) + re-zero for next replay ----------------
__global__ void k_scatter(const int* __restrict__ ei, int E) {
    int tid = blockIdx.x * blockDim.x + threadIdx.x;
    int t4 = tid * 4;
    if (t4 + 4 <= E) {
        int4 s = *(const int4*)(ei + t4);
        int4 d = *(const int4*)(ei + E + t4);
        g_esrc[atomicAdd(&g_cursor[d.x], 1)] = s.x;
        g_esrc[atomicAdd(&g_cursor[d.y], 1)] = s.y;
        g_esrc[atomicAdd(&g_cursor[d.z], 1)] = s.z;
        g_esrc[atomicAdd(&g_cursor[d.w], 1)] = s.w;
    } else {
        for (int e = t4; e < E; e++)
            g_esrc[atomicAdd(&g_cursor[ei[E + e]], 1)] = ei[e];
    }
    if (tid < NN) g_counts[tid] = 0;                       // counts consumed by k_scan
    if (tid < OUTC) { g_sum[tid] = 0.f; g_sumsq[tid] = 0.f; }
}

// ---------------- K4: gemm, packed f32x2 FMA ----------------
__global__ __launch_bounds__(256) void k_gemm(const float* __restrict__ x,
                                              const float* __restrict__ w,
                                              const float* __restrict__ bias) {
    __shared__ float sxT[128 * 32];   // [k][node]
    int n0 = blockIdx.x * 32;
    int b  = n0 >> 13;
    int s0 = n0 & 8191;
    int t  = threadIdx.x;

    const float* xb = x + (size_t)b * (CIN * DHW) + s0;
    for (int idx = t; idx < 128 * 32; idx += 256) {
        int k = idx >> 5, j = idx & 31;
        sxT[idx] = xb[(size_t)k * DHW + j];
    }
    __syncthreads();

    unsigned long long acc[16];
#pragma unroll
    for (int p = 0; p < 16; p++) acc[p] = 0ull;

    const float* wp = w + t;
    for (int k0 = 0; k0 < 128; k0 += 8) {
        float wr[8];
#pragma unroll
        for (int k = 0; k < 8; k++) wr[k] = wp[(size_t)(k0 + k) * HTOT];
#pragma unroll
        for (int k = 0; k < 8; k++) {
            unsigned long long wpk;
            asm("mov.b64 %0, {%1, %1};" : "=l"(wpk) : "r"(__float_as_uint(wr[k])));
            const unsigned long long* row =
                (const unsigned long long*)(sxT + (k0 + k) * 32);
#pragma unroll
            for (int p = 0; p < 16; p++) {
                asm("fma.rn.f32x2 %0, %1, %2, %0;"
                    : "+l"(acc[p]) : "l"(row[p]), "l"(wpk));
            }
        }
    }

    float bv = bias[t];
#pragma unroll
    for (int p = 0; p < 16; p++) {
        unsigned int lo, hi;
        asm("mov.b64 {%0, %1}, %2;" : "=r"(lo), "=r"(hi) : "l"(acc[p]));
        g_h[(size_t)(n0 + 2 * p)     * HTOT + t] = __uint_as_float(lo) + bv;
        g_h[(size_t)(n0 + 2 * p + 1) * HTOT + t] = __uint_as_float(hi) + bv;
    }
}

// ---------------- K5: GATv2 aggregation ----------------
// one warp per dst node; un-stabilized softmax (logits O(+-10), fp32-safe);
// 2-edge software pipeline: next pair's loads issued before current pair's math.
__global__ __launch_bounds__(256) void k_agg(const float* __restrict__ att,
                                             const float* __restrict__ gbias) {
    int t = threadIdx.x;
    int lane = t & 31;
    int n = blockIdx.x * 8 + (t >> 5);
    int off = lane * 8;

    float av[8], hd[8];
    {
        float4 a0 = *(const float4*)(att + off);
        float4 a1 = *(const float4*)(att + off + 4);
        av[0]=a0.x; av[1]=a0.y; av[2]=a0.z; av[3]=a0.w;
        av[4]=a1.x; av[5]=a1.y; av[6]=a1.z; av[7]=a1.w;
        const float* hr = g_h + (size_t)n * HTOT + off;
        float4 d0 = *(const float4*)(hr);
        float4 d1 = *(const float4*)(hr + 4);
        hd[0]=d0.x; hd[1]=d0.y; hd[2]=d0.z; hd[3]=d0.w;
        hd[4]=d1.x; hd[5]=d1.y; hd[6]=d1.z; hd[7]=d1.w;
    }

    // self-loop
    float loc = 0.f;
#pragma unroll
    for (int i = 0; i < 8; i++) {
        float v = 2.f * hd[i];
        v = fmaxf(v, NEG_ATT * v);
        loc = fmaf(av[i], v, loc);
    }
#pragma unroll
    for (int o = 8; o >= 1; o >>= 1) loc += __shfl_xor_sync(0xffffffffu, loc, o);
    float ps = __expf(loc);
    float den = ps;
    float acc[8];
#pragma unroll
    for (int i = 0; i < 8; i++) acc[i] = ps * hd[i];

    int rs = g_rowstart[n];
    int re = g_rowstart[n + 1];

    // process one resident pair held in (c00,c01,c10,c11)
    auto process_pair = [&](float4 c00, float4 c01, float4 c10, float4 c11) {
        float hs0[8] = {c00.x,c00.y,c00.z,c00.w,c01.x,c01.y,c01.z,c01.w};
        float hs1[8] = {c10.x,c10.y,c10.z,c10.w,c11.x,c11.y,c11.z,c11.w};
        float l0 = 0.f, l1 = 0.f;
#pragma unroll
        for (int i = 0; i < 8; i++) {
            float v0 = hd[i] + hs0[i]; v0 = fmaxf(v0, NEG_ATT * v0); l0 = fmaf(av[i], v0, l0);
            float v1 = hd[i] + hs1[i]; v1 = fmaxf(v1, NEG_ATT * v1); l1 = fmaf(av[i], v1, l1);
        }
#pragma unroll
        for (int o = 8; o >= 1; o >>= 1) {
            l0 += __shfl_xor_sync(0xffffffffu, l0, o);
            l1 += __shfl_xor_sync(0xffffffffu, l1, o);
        }
        float p0 = __expf(l0);
        float p1 = __expf(l1);
        den += p0 + p1;
#pragma unroll
        for (int i = 0; i < 8; i++)
            acc[i] = fmaf(p1, hs1[i], fmaf(p0, hs0[i], acc[i]));
    };

    int j = rs;
    if (j + 2 <= re) {
        const float* p0 = g_h + (size_t)g_esrc[j]     * HTOT + off;
        const float* p1 = g_h + (size_t)g_esrc[j + 1] * HTOT + off;
        float4 c00 = *(const float4*)(p0), c01 = *(const float4*)(p0 + 4);
        float4 c10 = *(const float4*)(p1), c11 = *(const float4*)(p1 + 4);
        j += 2;
        while (j + 2 <= re) {
            const float* q0 = g_h + (size_t)g_esrc[j]     * HTOT + off;
            const float* q1 = g_h + (size_t)g_esrc[j + 1] * HTOT + off;
            float4 d00 = *(const float4*)(q0), d01 = *(const float4*)(q0 + 4);
            float4 d10 = *(const float4*)(q1), d11 = *(const float4*)(q1 + 4);
            process_pair(c00, c01, c10, c11);   // loads above in flight
            c00 = d00; c01 = d01; c10 = d10; c11 = d11;
            j += 2;
        }
        process_pair(c00, c01, c10, c11);
    }
    for (; j < re; j++) {   // tail: 0 or 1 edge (or 1-edge rows)
        const float* r0 = g_h + (size_t)g_esrc[j] * HTOT + off;
        float4 x0 = *(const float4*)(r0), x1 = *(const float4*)(r0 + 4);
        float hs0[8] = {x0.x,x0.y,x0.z,x0.w,x1.x,x1.y,x1.z,x1.w};
        float l0 = 0.f;
#pragma unroll
        for (int i = 0; i < 8; i++) {
            float v0 = hd[i] + hs0[i];
            v0 = fmaxf(v0, NEG_ATT * v0);
            l0 = fmaf(av[i], v0, l0);
        }
#pragma unroll
        for (int o = 8; o >= 1; o >>= 1) l0 += __shfl_xor_sync(0xffffffffu, l0, o);
        float p0 = __expf(l0);
        den += p0;
#pragma unroll
        for (int i = 0; i < 8; i++) acc[i] = fmaf(p0, hs0[i], acc[i]);
    }

    float inv = 1.f / den;
    float v8[8], o8[8];
#pragma unroll
    for (int i = 0; i < 8; i++) v8[i] = acc[i] * inv;
#pragma unroll
    for (int i = 0; i < 8; i++) {
        float other = __shfl_down_sync(0xffffffffu, v8[i], 16);
        o8[i] = 0.5f * (v8[i] + other);
    }
    if (lane < 16) {
#pragma unroll
        for (int i = 0; i < 8; i++) o8[i] += gbias[off + i];
        float* op = g_pre + (size_t)n * OUTC + off;
        *(float4*)(op)     = make_float4(o8[0], o8[1], o8[2], o8[3]);
        *(float4*)(op + 4) = make_float4(o8[4], o8[5], o8[6], o8[7]);
    }
}

// ---------------- K6: BN partial sums ----------------
__global__ void k_bnred() {
    int c = threadIdx.x;           // 128 threads
    int n0 = blockIdx.x * 128;     // 128 blocks
    float s = 0.f, q = 0.f;
    for (int j = 0; j < 128; j++) {
        float v = g_pre[(size_t)(n0 + j) * OUTC + c];
        s += v;
        q = fmaf(v, v, q);
    }
    atomicAdd(&g_sum[c], s);
    atomicAdd(&g_sumsq[c], q);
}

// ---------------- K7: BN finalize + transpose + LeakyReLU ----------------
__global__ __launch_bounds__(256) void k_apply(const float* __restrict__ gamma,
                                               const float* __restrict__ beta,
                                               float* __restrict__ out) {
    __shared__ float tile[128 * 33];
    __shared__ float sc[128], sh[128];
    int t = threadIdx.x;
    if (t < 128) {
        float mean = g_sum[t] * (1.f / NN);
        float var  = g_sumsq[t] * (1.f / NN) - mean * mean;
        float inv  = rsqrtf(var + BN_EPS);
        float s    = gamma[t] * inv;
        sc[t] = s;
        sh[t] = beta[t] - mean * s;
    }
    int n0 = blockIdx.x * 32;
    for (int idx = t; idx < 4096; idx += 256) {
        int row = idx >> 7;
        int col = idx & 127;
        tile[col * 33 + row] = g_pre[(size_t)(n0 + row) * OUTC + col];
    }
    __syncthreads();
    int b  = n0 >> 13;
    int s0 = n0 & 8191;
    int sl = t & 31;
    int c0 = t >> 5;
    float* ob = out + (size_t)b * OUTC * DHW + s0 + sl;
#pragma unroll
    for (int pass = 0; pass < 16; pass++) {
        int c = pass * 8 + c0;
        float v = tile[c * 33 + sl];
        v = fmaf(v, sc[c], sh[c]);
        v = fmaxf(v, NEG_ACT * v);
        ob[(size_t)c * DHW] = v;
    }
}

// ---------------- launcher ----------------
extern "C" void kernel_launch(void* const* d_in, const int* in_sizes, int n_in,
                              void* d_out, int out_size) {
    const float* x     = (const float*)d_in[0];
    const int*   ei    = (const int*)d_in[1];
    const float* lin_w = (const float*)d_in[2];
    const float* lin_b = (const float*)d_in[3];
    const float* att   = (const float*)d_in[4];
    const float* gbias = (const float*)d_in[5];
    const float* gamma = (const float*)d_in[6];
    const float* beta  = (const float*)d_in[7];
    float* out = (float*)d_out;

    int E   = in_sizes[1] / 2;
    int cb4 = (E / 4 + 255) / 256;   // 4 edges per thread

    k_count<<<cb4, 256>>>(ei, E);
    k_scan<<<1, 512>>>();
    k_scatter<<<cb4, 256>>>(ei, E);
    k_gemm<<<NN / 32, 256>>>(x, lin_w, lin_b);
    k_agg<<<NN / 8, 256>>>(att, gbias);
    k_bnred<<<NN / 128, 128>>>();
    k_apply<<<NN / 32, 256>>>(gamma, beta, out);
}